// round 1
// baseline (speedup 1.0000x reference)
#include <cuda_runtime.h>
#include <cuda_bf16.h>

#define BATCH 2048
#define NCLS  1000
#define NCLSP 1024
#define FDIM  128

#define BM 128
#define BN 128
#define KC 32

__device__ float g_fn[BATCH];
__device__ float g_cn[NCLSP];
__device__ int   g_lab64;

// ---------------------------------------------------------------------------
// prep: row norms for feat (2048) and centers (1000, zero-padded to 1024),
// label dtype detection (int32 vs int64), likelihood slot zero-init.
// One warp per row. grid = 384 blocks x 256 threads (3072 warps).
// ---------------------------------------------------------------------------
__global__ __launch_bounds__(256) void lgm_prep(const float* __restrict__ feat,
                                                const float* __restrict__ centers,
                                                const int*   __restrict__ labelw,
                                                float* __restrict__ out) {
    int gid  = blockIdx.x * blockDim.x + threadIdx.x;
    int warp = gid >> 5;
    int lane = gid & 31;

    // label dtype detection: for int64 little-endian labels (<1000), every odd
    // int32 word in the first 2048 words is a zero high-half. For genuine
    // int32 labels those words are random labels. Stays in-bounds either way.
    if (gid < 32) {
        int nz = 0;
        for (int i = 2 * lane + 1; i < BATCH; i += 64) nz |= labelw[i];
        unsigned any = __ballot_sync(0xffffffffu, nz != 0);
        if (lane == 0) {
            g_lab64 = (any == 0u) ? 1 : 0;
            out[2 * BATCH * NCLS] = 0.0f;   // likelihood accumulator
        }
    }

    float s = 0.0f;
    if (warp < BATCH) {
        float4 v = ((const float4*)(feat + (size_t)warp * FDIM))[lane];
        s = v.x * v.x + v.y * v.y + v.z * v.z + v.w * v.w;
        #pragma unroll
        for (int o = 16; o > 0; o >>= 1) s += __shfl_xor_sync(0xffffffffu, s, o);
        if (lane == 0) g_fn[warp] = s;
    } else if (warp < BATCH + NCLSP) {
        int c = warp - BATCH;
        if (c < NCLS) {
            float4 v = ((const float4*)(centers + (size_t)c * FDIM))[lane];
            s = v.x * v.x + v.y * v.y + v.z * v.z + v.w * v.w;
            #pragma unroll
            for (int o = 16; o > 0; o >>= 1) s += __shfl_xor_sync(0xffffffffu, s, o);
            if (lane == 0) g_cn[c] = s;
        } else {
            if (lane == 0) g_cn[c] = 0.0f;
        }
    }
}

// ---------------------------------------------------------------------------
// main: 128x128 output tile per block, 8x8 per thread, KC=32 K-chunks.
// dist = fn + cn - 2*dot ; logits = -0.5*dist ; margin = 2*logits on the
// true class (ALPHA=1) ; likelihood += dist/(2B) on the true class.
// grid = (8 n-tiles, 16 m-tiles), 256 threads.
// ---------------------------------------------------------------------------
__global__ __launch_bounds__(256) void lgm_main(const float* __restrict__ feat,
                                                const float* __restrict__ centers,
                                                const void*  __restrict__ label,
                                                float* __restrict__ out) {
    __shared__ float As[KC][BM];   // As[k][m] = feat[bm+m][kb+k]
    __shared__ float Bs[KC][BN];   // Bs[k][n] = centers[bn+n][kb+k]

    const int bm = blockIdx.y * BM;
    const int bn = blockIdx.x * BN;
    const int t  = threadIdx.x;
    const int tm = (t >> 4) << 3;   // 0..120
    const int tn = (t & 15) << 3;   // 0..120

    float acc[8][8];
    #pragma unroll
    for (int i = 0; i < 8; i++)
        #pragma unroll
        for (int j = 0; j < 8; j++) acc[i][j] = 0.0f;

    for (int kb = 0; kb < FDIM; kb += KC) {
        // Stage tiles transposed. 1024 float4 per operand; 4 per thread.
        // Within a warp, m is lane-consecutive -> conflict-free STS.
        #pragma unroll
        for (int i = 0; i < 4; i++) {
            int f  = t + (i << 8);      // 0..1023
            int m  = f & 127;
            int kc = f >> 7;            // 0..7 float4 chunk within KC
            float4 va = *(const float4*)(feat + (size_t)(bm + m) * FDIM + kb + (kc << 2));
            As[(kc << 2) + 0][m] = va.x;
            As[(kc << 2) + 1][m] = va.y;
            As[(kc << 2) + 2][m] = va.z;
            As[(kc << 2) + 3][m] = va.w;
            int c = bn + m;
            float4 vb = make_float4(0.f, 0.f, 0.f, 0.f);
            if (c < NCLS)
                vb = *(const float4*)(centers + (size_t)c * FDIM + kb + (kc << 2));
            Bs[(kc << 2) + 0][m] = vb.x;
            Bs[(kc << 2) + 1][m] = vb.y;
            Bs[(kc << 2) + 2][m] = vb.z;
            Bs[(kc << 2) + 3][m] = vb.w;
        }
        __syncthreads();

        #pragma unroll
        for (int k = 0; k < KC; k++) {
            float4 a0 = *(const float4*)&As[k][tm];
            float4 a1 = *(const float4*)&As[k][tm + 4];
            float4 b0 = *(const float4*)&Bs[k][tn];
            float4 b1 = *(const float4*)&Bs[k][tn + 4];
            float ar[8] = {a0.x, a0.y, a0.z, a0.w, a1.x, a1.y, a1.z, a1.w};
            float br[8] = {b0.x, b0.y, b0.z, b0.w, b1.x, b1.y, b1.z, b1.w};
            #pragma unroll
            for (int i = 0; i < 8; i++)
                #pragma unroll
                for (int j = 0; j < 8; j++)
                    acc[i][j] = fmaf(ar[i], br[j], acc[i][j]);
        }
        __syncthreads();
    }

    // ---- epilogue ----
    const bool l64 = (g_lab64 != 0);
    const long long* lab64 = (const long long*)label;
    const int*       lab32 = (const int*)label;

    float fn[8], cn[8];
    int lab[8];
    #pragma unroll
    for (int i = 0; i < 8; i++) {
        int b = bm + tm + i;
        fn[i]  = g_fn[b];
        lab[i] = l64 ? (int)lab64[b] : lab32[b];
    }
    #pragma unroll
    for (int j = 0; j < 8; j++) {
        cn[j] = g_cn[bn + tn + j];   // bn+tn+j < 1024, zero-padded region OK
    }

    float lik = 0.0f;
    float* __restrict__ mout = out + (size_t)BATCH * NCLS;

    #pragma unroll
    for (int i = 0; i < 8; i++) {
        int b = bm + tm + i;
        #pragma unroll
        for (int jj = 0; jj < 8; jj += 4) {
            int c0 = bn + tn + jj;
            if (c0 < NCLS) {   // NCLS % 4 == 0, so float4 groups never split
                float lv[4], mv[4];
                #pragma unroll
                for (int j = 0; j < 4; j++) {
                    int   c    = c0 + j;
                    float dist = fn[i] + cn[jj + j] - 2.0f * acc[i][jj + j];
                    float lg   = -0.5f * dist;
                    bool  hit  = (c == lab[i]);
                    lv[j] = lg;
                    mv[j] = hit ? 2.0f * lg : lg;
                    if (hit) lik += dist;
                }
                *(float4*)(out  + (size_t)b * NCLS + c0) = make_float4(lv[0], lv[1], lv[2], lv[3]);
                *(float4*)(mout + (size_t)b * NCLS + c0) = make_float4(mv[0], mv[1], mv[2], mv[3]);
            }
        }
    }

    if (lik != 0.0f)
        atomicAdd(out + 2 * (size_t)BATCH * NCLS, lik * (1.0f / (2.0f * (float)BATCH)));
}

extern "C" void kernel_launch(void* const* d_in, const int* in_sizes, int n_in,
                              void* d_out, int out_size) {
    const float* feat    = (const float*)d_in[0];
    const void*  label   = d_in[1];
    const float* centers = (const float*)d_in[2];
    float* out = (float*)d_out;

    lgm_prep<<<384, 256>>>(feat, centers, (const int*)label, out);

    dim3 grid(8, 16);   // 8 n-tiles x 16 m-tiles
    lgm_main<<<grid, 256>>>(feat, centers, label, out);
}

// round 3
// speedup vs baseline: 2.0290x; 2.0290x over previous
#include <cuda_runtime.h>
#include <cuda_bf16.h>
#include <cstdint>

#define BATCH 2048
#define NCLS  1000
#define NCLSP 1024
#define FDIM  128

#define BM 128
#define BN 128
#define KC 64
#define RSTRIDE 144   // bytes per staged row (64 bf16 + 8 pad)

__device__ float g_fn[BATCH];
__device__ float g_cn[NCLSP];
__device__ int   g_lab64;
__device__ __nv_bfloat16 g_featb[BATCH * FDIM];
__device__ __nv_bfloat16 g_cenb[NCLSP * FDIM];

__device__ __forceinline__ uint32_t smem_to_u32(const void* p) {
    uint32_t a;
    asm("{ .reg .u64 t; cvta.to.shared.u64 t, %1; cvt.u32.u64 %0, t; }" : "=r"(a) : "l"(p));
    return a;
}

__device__ __forceinline__ void ldm_x4(uint32_t* r, uint32_t addr) {
    asm volatile("ldmatrix.sync.aligned.m8n8.x4.shared.b16 {%0,%1,%2,%3}, [%4];"
                 : "=r"(r[0]), "=r"(r[1]), "=r"(r[2]), "=r"(r[3]) : "r"(addr));
}

__device__ __forceinline__ void mma_bf16(float* c, const uint32_t* a, const uint32_t* b) {
    asm volatile("mma.sync.aligned.m16n8k16.row.col.f32.bf16.bf16.f32 "
                 "{%0,%1,%2,%3}, {%4,%5,%6,%7}, {%8,%9}, {%0,%1,%2,%3};"
                 : "+f"(c[0]), "+f"(c[1]), "+f"(c[2]), "+f"(c[3])
                 : "r"(a[0]), "r"(a[1]), "r"(a[2]), "r"(a[3]), "r"(b[0]), "r"(b[1]));
}

// ---------------------------------------------------------------------------
// prep: fp32 row norms, bf16 copies of feat/centers (centers zero-padded to
// 1024 rows), label dtype detect, likelihood slot zero. One warp per row.
// ---------------------------------------------------------------------------
__global__ __launch_bounds__(256) void lgm_prep(const float* __restrict__ feat,
                                                const float* __restrict__ centers,
                                                const int*   __restrict__ labelw,
                                                float* __restrict__ out) {
    int gid  = blockIdx.x * blockDim.x + threadIdx.x;
    int warp = gid >> 5;
    int lane = gid & 31;

    if (gid < 32) {
        int nz = 0;
        for (int i = 2 * lane + 1; i < BATCH; i += 64) nz |= labelw[i];
        unsigned any = __ballot_sync(0xffffffffu, nz != 0);
        if (lane == 0) {
            g_lab64 = (any == 0u) ? 1 : 0;
            out[2 * BATCH * NCLS] = 0.0f;
        }
    }

    if (warp < BATCH) {
        float4 v = ((const float4*)(feat + (size_t)warp * FDIM))[lane];
        float s = v.x * v.x + v.y * v.y + v.z * v.z + v.w * v.w;
        #pragma unroll
        for (int o = 16; o > 0; o >>= 1) s += __shfl_xor_sync(0xffffffffu, s, o);
        if (lane == 0) g_fn[warp] = s;
        __nv_bfloat16* d = g_featb + (size_t)warp * FDIM + lane * 4;
        *(__nv_bfloat162*)(d)     = __nv_bfloat162(__float2bfloat16_rn(v.x), __float2bfloat16_rn(v.y));
        *(__nv_bfloat162*)(d + 2) = __nv_bfloat162(__float2bfloat16_rn(v.z), __float2bfloat16_rn(v.w));
    } else if (warp < BATCH + NCLSP) {
        int c = warp - BATCH;
        __nv_bfloat16* d = g_cenb + (size_t)c * FDIM + lane * 4;
        if (c < NCLS) {
            float4 v = ((const float4*)(centers + (size_t)c * FDIM))[lane];
            float s = v.x * v.x + v.y * v.y + v.z * v.z + v.w * v.w;
            #pragma unroll
            for (int o = 16; o > 0; o >>= 1) s += __shfl_xor_sync(0xffffffffu, s, o);
            if (lane == 0) g_cn[c] = s;
            *(__nv_bfloat162*)(d)     = __nv_bfloat162(__float2bfloat16_rn(v.x), __float2bfloat16_rn(v.y));
            *(__nv_bfloat162*)(d + 2) = __nv_bfloat162(__float2bfloat16_rn(v.z), __float2bfloat16_rn(v.w));
        } else {
            if (lane == 0) g_cn[c] = 0.0f;
            __nv_bfloat162 z(__float2bfloat16_rn(0.f), __float2bfloat16_rn(0.f));
            *(__nv_bfloat162*)(d) = z;
            *(__nv_bfloat162*)(d + 2) = z;
        }
    }
}

// ---------------------------------------------------------------------------
// main: bf16 HMMA (mma.sync m16n8k16), 128x128 tile/CTA, 8 warps (2m x 4n),
// warp tile 64x32 = 4x4 mma tiles. K=128 in two KC=64 smem chunks.
// dist = fn + cn - 2*dot ; logits = -0.5*dist ; margin doubles true class.
// ---------------------------------------------------------------------------
__global__ __launch_bounds__(256) void lgm_main(const void* __restrict__ label,
                                                float* __restrict__ out) {
    __shared__ __align__(16) unsigned char smem[2 * 128 * RSTRIDE + 512];
    unsigned char* As = smem;                       // 128 rows x 144B
    unsigned char* Bs = smem + 128 * RSTRIDE;       // 128 rows x 144B
    int* lab_s = (int*)(smem + 2 * 128 * RSTRIDE);  // 128 ints

    const int t    = threadIdx.x;
    const int wid  = t >> 5;
    const int lane = t & 31;
    const int bm   = blockIdx.y * BM;
    const int bn   = blockIdx.x * BN;
    const int wm   = wid & 1;    // 0..1  (64-row slab)
    const int wn   = wid >> 1;   // 0..3  (32-col slab)

    // labels -> smem
    const bool l64 = (g_lab64 != 0);
    if (t < 128) {
        int b = bm + t;
        lab_s[t] = l64 ? (int)((const long long*)label)[b] : ((const int*)label)[b];
    }

    float acc[4][4][4];
    #pragma unroll
    for (int mi = 0; mi < 4; mi++)
        #pragma unroll
        for (int ni = 0; ni < 4; ni++)
            #pragma unroll
            for (int r = 0; r < 4; r++) acc[mi][ni][r] = 0.0f;

    // per-lane ldmatrix base addresses
    const uint32_t sA = smem_to_u32(As);
    const uint32_t sB = smem_to_u32(Bs);
    // A x4: lanes 0-7 rows0-7/k0, 8-15 rows8-15/k0, 16-23 rows0-7/k8, 24-31 rows8-15/k8
    const uint32_t aBase = sA + (uint32_t)(wm * 64 + (lane & 15)) * RSTRIDE + (lane >> 4) * 16;
    // B x4 covers 2 n8 tiles: lanes 0-7 n0-7/k0, 8-15 n0-7/k8, 16-23 n8-15/k0, 24-31 n8-15/k8
    const uint32_t bBase = sB + (uint32_t)(wn * 32 + (lane & 7) + (lane >> 4) * 8) * RSTRIDE
                              + ((lane >> 3) & 1) * 16;

    #pragma unroll 1
    for (int kb = 0; kb < FDIM; kb += KC) {
        if (kb) __syncthreads();
        // stage 128 rows x 64 bf16 (8 x uint4 per row) per operand
        #pragma unroll
        for (int i = 0; i < 4; i++) {
            int idx = t + (i << 8);         // 0..1023
            int row = idx >> 3;
            int seg = idx & 7;
            *(uint4*)(As + row * RSTRIDE + seg * 16) =
                *(const uint4*)((const unsigned char*)g_featb + (size_t)(bm + row) * 256 + kb * 2 + seg * 16);
            *(uint4*)(Bs + row * RSTRIDE + seg * 16) =
                *(const uint4*)((const unsigned char*)g_cenb + (size_t)(bn + row) * 256 + kb * 2 + seg * 16);
        }
        __syncthreads();

        #pragma unroll
        for (int ks = 0; ks < KC / 16; ks++) {
            uint32_t a[4][4], b[2][4];
            #pragma unroll
            for (int mi = 0; mi < 4; mi++)
                ldm_x4(a[mi], aBase + (uint32_t)(mi * 16) * RSTRIDE + ks * 32);
            #pragma unroll
            for (int nj = 0; nj < 2; nj++)
                ldm_x4(b[nj], bBase + (uint32_t)(nj * 16) * RSTRIDE + ks * 32);
            #pragma unroll
            for (int mi = 0; mi < 4; mi++)
                #pragma unroll
                for (int ni = 0; ni < 4; ni++)
                    mma_bf16(acc[mi][ni], a[mi], &b[ni >> 1][(ni & 1) * 2]);
        }
    }
    // no sync needed after last chunk: each warp only reads its own accs now

    // ---- epilogue ----
    const int r4 = lane >> 2;          // 0..7
    const int c2 = (lane & 3) * 2;     // 0,2,4,6
    float* __restrict__ mout = out + (size_t)BATCH * NCLS;

    float cnv[4][2];
    #pragma unroll
    for (int ni = 0; ni < 4; ni++) {
        int c = bn + wn * 32 + ni * 8 + c2;
        cnv[ni][0] = g_cn[c];
        cnv[ni][1] = g_cn[c + 1];
    }

    float lik = 0.0f;
    #pragma unroll
    for (int mi = 0; mi < 4; mi++) {
        #pragma unroll
        for (int rh = 0; rh < 2; rh++) {
            int rloc = wm * 64 + mi * 16 + r4 + rh * 8;
            int b    = bm + rloc;
            float fn = g_fn[b];
            int   lb = lab_s[rloc];
            size_t rowoff = (size_t)b * NCLS;
            #pragma unroll
            for (int ni = 0; ni < 4; ni++) {
                int c0 = bn + wn * 32 + ni * 8 + c2;
                float d0 = acc[mi][ni][rh * 2 + 0];
                float d1 = acc[mi][ni][rh * 2 + 1];
                float dist0 = fn + cnv[ni][0] - 2.0f * d0;
                float dist1 = fn + cnv[ni][1] - 2.0f * d1;
                float l0 = -0.5f * dist0;
                float l1 = -0.5f * dist1;
                bool h0 = (c0 == lb);
                bool h1 = (c0 + 1 == lb);
                if (h0) lik += dist0;
                if (h1) lik += dist1;
                if (c0 < NCLS) {   // NCLS even, c0 even -> pair never splits
                    *(float2*)(out  + rowoff + c0) = make_float2(l0, l1);
                    *(float2*)(mout + rowoff + c0) = make_float2(h0 ? 2.0f * l0 : l0,
                                                                 h1 ? 2.0f * l1 : l1);
                }
            }
        }
    }

    #pragma unroll
    for (int o = 16; o > 0; o >>= 1) lik += __shfl_xor_sync(0xffffffffu, lik, o);
    if (lane == 0 && lik != 0.0f)
        atomicAdd(out + 2 * (size_t)BATCH * NCLS, lik * (1.0f / (2.0f * (float)BATCH)));
}

extern "C" void kernel_launch(void* const* d_in, const int* in_sizes, int n_in,
                              void* d_out, int out_size) {
    const float* feat    = (const float*)d_in[0];
    const void*  label   = d_in[1];
    const float* centers = (const float*)d_in[2];
    float* out = (float*)d_out;

    lgm_prep<<<384, 256>>>(feat, centers, (const int*)label, out);

    dim3 grid(NCLSP / BN, BATCH / BM);   // 8 x 16 = 128 CTAs
    lgm_main<<<grid, 256>>>(label, out);
}

// round 4
// speedup vs baseline: 2.2832x; 1.1253x over previous
#include <cuda_runtime.h>
#include <cuda_bf16.h>
#include <cstdint>

#define BATCH 2048
#define NCLS  1000
#define NCLSP 1024
#define FDIM  128

#define BM 128
#define BN 64
#define RSTRIDE 272          // 256B (128 bf16) + 16B pad: conflict-free, 16B aligned

#define SM_A 0
#define SM_B (128 * RSTRIDE)             // 34816
#define SM_LAB (SM_B + 64 * RSTRIDE)     // 52224
#define SMEM_BYTES (SM_LAB + 512)        // 52736

__device__ float g_fn[BATCH];
__device__ float g_cn[NCLSP];
__device__ int   g_lab64;
__device__ __nv_bfloat16 g_featb[BATCH * FDIM];
__device__ __nv_bfloat16 g_cenb[NCLSP * FDIM];

__device__ __forceinline__ uint32_t smem_to_u32(const void* p) {
    uint32_t a;
    asm("{ .reg .u64 t; cvta.to.shared.u64 t, %1; cvt.u32.u64 %0, t; }" : "=r"(a) : "l"(p));
    return a;
}
__device__ __forceinline__ void ldm_x4(uint32_t* r, uint32_t addr) {
    asm volatile("ldmatrix.sync.aligned.m8n8.x4.shared.b16 {%0,%1,%2,%3}, [%4];"
                 : "=r"(r[0]), "=r"(r[1]), "=r"(r[2]), "=r"(r[3]) : "r"(addr));
}
__device__ __forceinline__ void mma_bf16(float* c, const uint32_t* a, const uint32_t* b) {
    asm volatile("mma.sync.aligned.m16n8k16.row.col.f32.bf16.bf16.f32 "
                 "{%0,%1,%2,%3}, {%4,%5,%6,%7}, {%8,%9}, {%0,%1,%2,%3};"
                 : "+f"(c[0]), "+f"(c[1]), "+f"(c[2]), "+f"(c[3])
                 : "r"(a[0]), "r"(a[1]), "r"(a[2]), "r"(a[3]), "r"(b[0]), "r"(b[1]));
}
__device__ __forceinline__ void cp16(uint32_t dst, const void* src) {
    asm volatile("cp.async.cg.shared.global [%0], [%1], 16;" :: "r"(dst), "l"(src));
}

// ---------------------------------------------------------------------------
// prep: fp32 row norms, bf16 copies of feat/centers (centers zero-padded to
// 1024 rows), label dtype detect, likelihood slot zero. One warp per row.
// ---------------------------------------------------------------------------
__global__ __launch_bounds__(256) void lgm_prep(const float* __restrict__ feat,
                                                const float* __restrict__ centers,
                                                const int*   __restrict__ labelw,
                                                float* __restrict__ out) {
    int gid  = blockIdx.x * blockDim.x + threadIdx.x;
    int warp = gid >> 5;
    int lane = gid & 31;

    if (gid < 32) {
        int nz = 0;
        for (int i = 2 * lane + 1; i < BATCH; i += 64) nz |= labelw[i];
        unsigned any = __ballot_sync(0xffffffffu, nz != 0);
        if (lane == 0) {
            g_lab64 = (any == 0u) ? 1 : 0;
            out[2 * BATCH * NCLS] = 0.0f;
        }
    }

    if (warp < BATCH) {
        float4 v = ((const float4*)(feat + (size_t)warp * FDIM))[lane];
        float s = v.x * v.x + v.y * v.y + v.z * v.z + v.w * v.w;
        #pragma unroll
        for (int o = 16; o > 0; o >>= 1) s += __shfl_xor_sync(0xffffffffu, s, o);
        if (lane == 0) g_fn[warp] = s;
        __nv_bfloat16* d = g_featb + (size_t)warp * FDIM + lane * 4;
        *(__nv_bfloat162*)(d)     = __nv_bfloat162(__float2bfloat16_rn(v.x), __float2bfloat16_rn(v.y));
        *(__nv_bfloat162*)(d + 2) = __nv_bfloat162(__float2bfloat16_rn(v.z), __float2bfloat16_rn(v.w));
    } else if (warp < BATCH + NCLSP) {
        int c = warp - BATCH;
        __nv_bfloat16* d = g_cenb + (size_t)c * FDIM + lane * 4;
        if (c < NCLS) {
            float4 v = ((const float4*)(centers + (size_t)c * FDIM))[lane];
            float s = v.x * v.x + v.y * v.y + v.z * v.z + v.w * v.w;
            #pragma unroll
            for (int o = 16; o > 0; o >>= 1) s += __shfl_xor_sync(0xffffffffu, s, o);
            if (lane == 0) g_cn[c] = s;
            *(__nv_bfloat162*)(d)     = __nv_bfloat162(__float2bfloat16_rn(v.x), __float2bfloat16_rn(v.y));
            *(__nv_bfloat162*)(d + 2) = __nv_bfloat162(__float2bfloat16_rn(v.z), __float2bfloat16_rn(v.w));
        } else {
            if (lane == 0) g_cn[c] = 0.0f;
            __nv_bfloat162 z(__float2bfloat16_rn(0.f), __float2bfloat16_rn(0.f));
            *(__nv_bfloat162*)(d) = z;
            *(__nv_bfloat162*)(d + 2) = z;
        }
    }
}

// ---------------------------------------------------------------------------
// main: bf16 HMMA, 128x64 tile/CTA, grid 16x16 = 256 CTAs (2/SM).
// Single-stage K=128 in smem via cp.async; one syncthreads; 8 warps 4m x 2n,
// warp tile 32x32.
// ---------------------------------------------------------------------------
__global__ __launch_bounds__(256, 2) void lgm_main(const void* __restrict__ label,
                                                   float* __restrict__ out) {
    extern __shared__ __align__(16) unsigned char smem[];
    const uint32_t sb = smem_to_u32(smem);
    int* lab_s = (int*)(smem + SM_LAB);

    const int t    = threadIdx.x;
    const int wid  = t >> 5;
    const int lane = t & 31;
    const int bm   = blockIdx.y * BM;
    const int bn   = blockIdx.x * BN;
    const int wm   = wid & 3;    // 0..3 : 32-row slab
    const int wn   = wid >> 2;   // 0..1 : 32-col slab

    // stage A (128 rows) + B (64 rows), 16B per op, 12 ops/thread
    #pragma unroll
    for (int i = 0; i < 8; i++) {
        int idx = t + (i << 8);          // 0..2047
        int row = idx >> 4, seg = idx & 15;
        cp16(sb + SM_A + row * RSTRIDE + seg * 16,
             (const unsigned char*)g_featb + (size_t)(bm + row) * 256 + seg * 16);
    }
    #pragma unroll
    for (int i = 0; i < 4; i++) {
        int idx = t + (i << 8);          // 0..1023
        int row = idx >> 4, seg = idx & 15;
        cp16(sb + SM_B + row * RSTRIDE + seg * 16,
             (const unsigned char*)g_cenb + (size_t)(bn + row) * 256 + seg * 16);
    }
    asm volatile("cp.async.commit_group;" ::: "memory");

    // labels while copies fly
    const bool l64 = (g_lab64 != 0);
    if (t < BM) {
        int b = bm + t;
        lab_s[t] = l64 ? (int)((const long long*)label)[b] : ((const int*)label)[b];
    }

    float acc[2][4][4];
    #pragma unroll
    for (int mi = 0; mi < 2; mi++)
        #pragma unroll
        for (int ni = 0; ni < 4; ni++)
            #pragma unroll
            for (int r = 0; r < 4; r++) acc[mi][ni][r] = 0.0f;

    const uint32_t aBase = sb + SM_A + (uint32_t)(wm * 32 + (lane & 15)) * RSTRIDE + (lane >> 4) * 16;
    const uint32_t bBase = sb + SM_B + (uint32_t)(wn * 32 + (lane & 7) + (lane >> 4) * 8) * RSTRIDE
                              + ((lane >> 3) & 1) * 16;

    asm volatile("cp.async.wait_group 0;" ::: "memory");
    __syncthreads();

    #pragma unroll
    for (int ks = 0; ks < 8; ks++) {
        uint32_t a[2][4], b[2][4];
        #pragma unroll
        for (int mi = 0; mi < 2; mi++)
            ldm_x4(a[mi], aBase + (uint32_t)(mi * 16) * RSTRIDE + ks * 32);
        #pragma unroll
        for (int nj = 0; nj < 2; nj++)
            ldm_x4(b[nj], bBase + (uint32_t)(nj * 16) * RSTRIDE + ks * 32);
        #pragma unroll
        for (int mi = 0; mi < 2; mi++)
            #pragma unroll
            for (int ni = 0; ni < 4; ni++)
                mma_bf16(acc[mi][ni], a[mi], &b[ni >> 1][(ni & 1) * 2]);
    }

    // ---- epilogue ----
    const int r4 = lane >> 2;          // 0..7
    const int c2 = (lane & 3) * 2;     // 0,2,4,6
    float* __restrict__ mout = out + (size_t)BATCH * NCLS;

    float cnv[4][2];
    #pragma unroll
    for (int ni = 0; ni < 4; ni++) {
        int c = bn + wn * 32 + ni * 8 + c2;
        cnv[ni][0] = g_cn[c];
        cnv[ni][1] = g_cn[c + 1];
    }

    float lik = 0.0f;
    #pragma unroll
    for (int mi = 0; mi < 2; mi++) {
        #pragma unroll
        for (int rh = 0; rh < 2; rh++) {
            int rloc = wm * 32 + mi * 16 + rh * 8 + r4;
            int b    = bm + rloc;
            float fn = g_fn[b];
            int   lb = lab_s[rloc];
            size_t rowoff = (size_t)b * NCLS;
            #pragma unroll
            for (int ni = 0; ni < 4; ni++) {
                int c0 = bn + wn * 32 + ni * 8 + c2;
                float d0 = acc[mi][ni][rh * 2 + 0];
                float d1 = acc[mi][ni][rh * 2 + 1];
                float dist0 = fn + cnv[ni][0] - 2.0f * d0;
                float dist1 = fn + cnv[ni][1] - 2.0f * d1;
                float l0 = -0.5f * dist0;
                float l1 = -0.5f * dist1;
                bool h0 = (c0 == lb);
                bool h1 = (c0 + 1 == lb);
                if (h0) lik += dist0;
                if (h1) lik += dist1;
                if (c0 < NCLS) {   // NCLS even, c0 even -> pair never splits
                    *(float2*)(out  + rowoff + c0) = make_float2(l0, l1);
                    *(float2*)(mout + rowoff + c0) = make_float2(h0 ? 2.0f * l0 : l0,
                                                                 h1 ? 2.0f * l1 : l1);
                }
            }
        }
    }

    #pragma unroll
    for (int o = 16; o > 0; o >>= 1) lik += __shfl_xor_sync(0xffffffffu, lik, o);
    if (lane == 0 && lik != 0.0f)
        atomicAdd(out + 2 * (size_t)BATCH * NCLS, lik * (1.0f / (2.0f * (float)BATCH)));
}

extern "C" void kernel_launch(void* const* d_in, const int* in_sizes, int n_in,
                              void* d_out, int out_size) {
    const float* feat    = (const float*)d_in[0];
    const void*  label   = d_in[1];
    const float* centers = (const float*)d_in[2];
    float* out = (float*)d_out;

    cudaFuncSetAttribute(lgm_main, cudaFuncAttributeMaxDynamicSharedMemorySize, SMEM_BYTES);

    lgm_prep<<<384, 256>>>(feat, centers, (const int*)label, out);

    dim3 grid(NCLSP / BN, BATCH / BM);   // 16 x 16 = 256 CTAs
    lgm_main<<<grid, 256, SMEM_BYTES>>>(label, out);
}